// round 7
// baseline (speedup 1.0000x reference)
#include <cuda_runtime.h>
#include <math.h>

// Problem constants
#define BB   1024
#define NN   100
#define HH   128
#define STEPS 128
#define NEGV -1000000000.0f
#define NPAD 132

// packed f32x2 helpers (Blackwell FFMA2 — bit-identical per-lane IEEE fma)
#define PK2(d, x, y)  asm("mov.b64 %0, {%1, %2};" : "=l"(d) : "f"(x), "f"(y))
#define UPK2(x, y, d) asm("mov.b64 {%0, %1}, %2;" : "=f"(x), "=f"(y) : "l"(d))
#define FMA2(d, a, b) asm("fma.rn.f32x2 %0, %1, %2, %0;" : "+l"(d) : "l"(a), "l"(b))

// -------- device scratch ----
__device__ float g_K [BB*NN*HH];
__device__ float g_V [BB*NN*HH];
__device__ float g_K2[BB*NN*HH];
__device__ float g_Qe[BB*NN*HH];
__device__ float g_qpool[BB*HH];
__device__ float g_Wqf[HH*(HH+1)];
__device__ float g_WfoldT[HH*HH];
__device__ float g_Wpq[HH*HH];

// ======================= fold kernel =================================
__global__ void fold_kernel(const float* __restrict__ fc_w,
                            const float* __restrict__ fc1_w,
                            const float* __restrict__ Wq,
                            const float* __restrict__ Wo,
                            const float* __restrict__ Wk2)
{
    int mat = blockIdx.y;
    int r   = blockIdx.x;
    int j   = threadIdx.x;
    if (mat == 0) {
        if (j < 129) {
            float acc = 0.f;
            #pragma unroll 8
            for (int i = 0; i < 128; i++) acc += Wq[r*128 + i] * fc_w[i*129 + j];
            g_Wqf[r*129 + j] = 0.25f * acc;
        }
    } else if (mat == 1) {
        if (j < 128) {
            float acc = 0.f;
            #pragma unroll 8
            for (int i = 0; i < 128; i++) acc += Wk2[i*128 + j] * Wo[i*128 + r];
            g_WfoldT[r*128 + j] = (1.0f / sqrtf(128.0f)) * acc;
        }
    } else {
        if (j < 128) {
            float acc = 0.f;
            #pragma unroll 8
            for (int i = 0; i < 128; i++) acc += Wq[r*128 + i] * fc1_w[i*128 + j];
            g_Wpq[r*128 + j] = 0.25f * acc;
        }
    }
}

// ======================= GEMM: out = A @ W^T (FFMA2) ========================
#define GM_TILE 64
#define GEMM_SMEM ((128*132 + GM_TILE*132) * 4)

__global__ __launch_bounds__(256) void gemm_kernel(const float* __restrict__ enc,
                                                   const float* __restrict__ pool,
                                                   const float* __restrict__ Wk,
                                                   const float* __restrict__ Wv)
{
    extern __shared__ float sm[];
    float* sW = sm;
    float* sA = sm + 128*132;

    int slice = blockIdx.y;
    const float* A; const float* W; float* O; int rows; int ldw = 128;
    if      (slice == 0) { A = enc;  W = Wk;       O = g_K;     rows = BB*NN; }
    else if (slice == 1) { A = enc;  W = Wv;       O = g_V;     rows = BB*NN; }
    else if (slice == 2) { A = enc;  W = g_WfoldT; O = g_K2;    rows = BB*NN; }
    else if (slice == 3) { A = enc;  W = g_Wqf;    O = g_Qe;    rows = BB*NN; ldw = 129; }
    else                 { A = pool; W = g_Wpq;    O = g_qpool; rows = BB;    }

    int row0 = blockIdx.x * GM_TILE;
    if (row0 >= rows) return;
    int tid = threadIdx.x;

    for (int i = tid; i < 128*128; i += 256) {
        int c = i >> 7, m = i & 127;
        sW[m*132 + c] = W[c*ldw + m];
    }
    for (int i = tid; i < GM_TILE*128; i += 256) {
        int r = i >> 7, k = i & 127;
        sA[r*132 + k] = A[(row0 + r)*128 + k];
    }
    __syncthreads();

    int warp = tid >> 5, lane = tid & 31;
    int r0 = warp * 8, c0 = lane * 4;

    unsigned long long accp[4][4];
    #pragma unroll
    for (int c = 0; c < 4; c++)
        #pragma unroll
        for (int t = 0; t < 4; t++) PK2(accp[c][t], 0.f, 0.f);

    #pragma unroll 4
    for (int k = 0; k < 128; k++) {
        float4 w4 = *(const float4*)&sW[k*132 + c0];
        unsigned long long wd[4];
        PK2(wd[0], w4.x, w4.x); PK2(wd[1], w4.y, w4.y);
        PK2(wd[2], w4.z, w4.z); PK2(wd[3], w4.w, w4.w);
        unsigned long long ap[4];
        #pragma unroll
        for (int t = 0; t < 4; t++) {
            float a0 = sA[(r0 + 2*t    )*132 + k];
            float a1 = sA[(r0 + 2*t + 1)*132 + k];
            PK2(ap[t], a0, a1);
        }
        #pragma unroll
        for (int c = 0; c < 4; c++)
            #pragma unroll
            for (int t = 0; t < 4; t++) FMA2(accp[c][t], ap[t], wd[c]);
    }

    #pragma unroll
    for (int t = 0; t < 4; t++) {
        float4 v0, v1;
        UPK2(v0.x, v1.x, accp[0][t]);
        UPK2(v0.y, v1.y, accp[1][t]);
        UPK2(v0.z, v1.z, accp[2][t]);
        UPK2(v0.w, v1.w, accp[3][t]);
        *(float4*)&O[(size_t)(row0 + r0 + 2*t    )*128 + c0] = v0;
        *(float4*)&O[(size_t)(row0 + r0 + 2*t + 1)*128 + c0] = v1;
    }
}

// ======================= decode kernel ======================================
// 1 CTA per batch row; 256 threads; K, K2, Qe ALL smem-resident; V in regs;
// mask state replicated in per-warp registers. Zero DRAM reads in the loop.
// smem: 3*13200 + 832 + 8 + 256 + 128*5 + 104 = 41440 floats = 165.76 KB
#define DEC_SMEM_FLOATS (3*NN*NPAD + 832 + 8 + 256 + 128 + 128 + 128 + 128 + 128 + 104)
#define DEC_SMEM (DEC_SMEM_FLOATS * 4)

__global__ __launch_bounds__(256, 1) void decode_kernel(const float* __restrict__ capacity,
                                                        const float* __restrict__ demand,
                                                        float* __restrict__ out)
{
    extern __shared__ float sm[];
    float* sK    = sm;                    // [100][132]
    float* sK2   = sK    + NN*NPAD;       // [100][132]
    float* sQe   = sK2   + NN*NPAD;       // [100][132]
    float* sAttn = sQe   + NN*NPAD;       // [8][104] halves at +0/+52 (unnormalized e)
    float* sRden = sAttn + 832;           // 8
    float* sPartA= sRden + 8;             // 256
    float* sG    = sPartA+ 256;           // 128
    float* sU    = sG    + 128;           // 128 (pads 100..127 = -inf)
    float* sQ    = sU    + 128;           // 128
    float* sWc   = sQ    + 128;           // 128
    float* sQp   = sWc   + 128;           // 128
    float* sDem  = sQp   + 128;           // 104

    __shared__ int sIdx;

    int b = blockIdx.x, tid = threadIdx.x;
    int warp = tid >> 5, lane = tid & 31;
    int d = tid & 127, half = tid >> 7, hh = d >> 4;

    // ---- bulk loads ----
    {
        const float4* gK  = (const float4*)(g_K  + (size_t)b*NN*HH);
        const float4* gK2 = (const float4*)(g_K2 + (size_t)b*NN*HH);
        const float4* gQe = (const float4*)(g_Qe + (size_t)b*NN*HH);
        for (int j = tid; j < NN*HH/4; j += 256) {
            int n = j >> 5; int c = (j & 31) << 2; int dd = n*NPAD + c;
            *(float4*)&sK [dd] = gK [j];
            *(float4*)&sK2[dd] = gK2[j];
            *(float4*)&sQe[dd] = gQe[j];
        }
    }
    float vreg[50];
    {
        const float* vg = g_V + (size_t)b*NN*HH + (size_t)(half*50)*HH + d;
        #pragma unroll
        for (int i = 0; i < 50; i++) vreg[i] = vg[i*HH];
    }
    if (tid < 128) { sWc[tid] = g_Wqf[tid*129 + 128]; sQp[tid] = g_qpool[b*HH + tid]; }
    if (tid < 100) sDem[tid] = demand[b*NN + tid];
    if (tid >= 100 && tid < 104) sDem[tid] = 0.f;
    if (tid >= 100 && tid < 128) sU[tid] = -INFINITY;   // argmax pads (never rewritten)
    __syncthreads();

    const float base_cap = capacity[0];
    float cap = capacity[b];

    // ---- per-thread replicated decode state ----
    float demreg[4];
    #pragma unroll
    for (int k = 0; k < 4; k++) { int n = lane + 32*k; demreg[k] = (n < 100) ? sDem[n] : 0.f; }
    float demSelf = (tid < 100) ? sDem[tid] : 0.f;

    unsigned m1bits = 0; int vis = 0;
    float maskreg[4]; float maskSelf;

    // initial mask: index=0, mask1=0, go_depot=1 (computed identically by all warps)
    {
        int cnt = 0;
        #pragma unroll
        for (int k = 0; k < 4; k++) {
            int n = lane + 32*k;
            float m = (demreg[k] > cap) ? 1.f : 0.f;
            unsigned bal = __ballot_sync(0xffffffffu, (n >= 1 && n < 100) && m == 0.f);
            cnt += __popc(bal);
            maskreg[k] = m;
        }
        float m0 = (cnt == 0) ? 0.f : 1.f;
        if (lane == 0) maskreg[0] = m0;
        maskSelf = (tid == 0) ? m0 : ((demSelf > cap) ? 1.f : 0.f);
    }
    // initial q (idx = 0)
    if (tid < 128) sQ[tid] = sQe[tid] + sWc[tid]*cap + sQp[tid];
    __syncthreads();

    float logTot = 0.f;
    int sStop = STEPS;

    for (int s = 0; s < STEPS; s++) {
        // ---- B: scores = dot16(q_h, K[n,h]); e=exp (no max-sub); per-head 1/sum ----
        {
            const float4* qp4 = (const float4*)&sQ[warp*16];
            float4 q0 = qp4[0], q1 = qp4[1], q2 = qp4[2], q3 = qp4[3];
            float e[4]; float sum = 0.f;
            #pragma unroll
            for (int k = 0; k < 4; k++) {
                int n = lane + 32*k;
                float ee = 0.f;
                if (n < 100) {
                    float v;
                    if (maskreg[k] > 0.f) v = NEGV;
                    else {
                        const float4* kp = (const float4*)&sK[n*NPAD + warp*16];
                        float4 a0=kp[0], a1=kp[1], a2=kp[2], a3=kp[3];
                        v = a0.x*q0.x + a0.y*q0.y + a0.z*q0.z + a0.w*q0.w
                          + a1.x*q1.x + a1.y*q1.y + a1.z*q1.z + a1.w*q1.w
                          + a2.x*q2.x + a2.y*q2.y + a2.z*q2.z + a2.w*q2.w
                          + a3.x*q3.x + a3.y*q3.y + a3.z*q3.z + a3.w*q3.w;
                    }
                    ee = __expf(v);
                }
                e[k] = ee; sum += ee;
            }
            #pragma unroll
            for (int o = 16; o; o >>= 1) sum += __shfl_xor_sync(0xffffffffu, sum, o);
            #pragma unroll
            for (int k = 0; k < 4; k++) {
                int n = lane + 32*k;
                if (n < 100) sAttn[warp*104 + n + ((n >= 50) ? 2 : 0)] = e[k];
            }
            if (lane == 0) sRden[warp] = 1.0f / sum;
        }
        __syncthreads();

        // ---- C: glimpse partials (V in regs, 4 accumulators) ----
        {
            const float* an = sAttn + hh*104 + half*52;
            float a0 = 0.f, a1 = 0.f, a2 = 0.f, a3 = 0.f;
            #pragma unroll
            for (int i = 0; i < 48; i += 4) {
                float4 a4 = *(const float4*)&an[i];
                a0 = fmaf(a4.x, vreg[i],   a0);
                a1 = fmaf(a4.y, vreg[i+1], a1);
                a2 = fmaf(a4.z, vreg[i+2], a2);
                a3 = fmaf(a4.w, vreg[i+3], a3);
            }
            a0 = fmaf(an[48], vreg[48], a0);
            a1 = fmaf(an[49], vreg[49], a1);
            sPartA[tid] = (a0 + a1) + (a2 + a3);
        }
        __syncthreads();

        float uv[4]; float vmax = -INFINITY; int imaxr = 0;

        // ---- warps 0-3: g-combine (deferred 1/sum), u, argmax ----
        if (tid < 128) {
            sG[tid] = (sPartA[tid] + sPartA[tid + 128]) * sRden[hh];
            asm volatile("bar.sync 1, 128;" ::: "memory");

            if (tid < 100) {
                const float* kp = sK2 + tid*NPAD;
                float b0 = 0.f, b1 = 0.f, b2 = 0.f, b3 = 0.f;
                #pragma unroll
                for (int j = 0; j < 128; j += 16) {
                    float4 x, g;
                    x = *(const float4*)&kp[j];    g = *(const float4*)&sG[j];
                    b0 = fmaf(x.x,g.x,b0); b0 = fmaf(x.y,g.y,b0); b0 = fmaf(x.z,g.z,b0); b0 = fmaf(x.w,g.w,b0);
                    x = *(const float4*)&kp[j+4];  g = *(const float4*)&sG[j+4];
                    b1 = fmaf(x.x,g.x,b1); b1 = fmaf(x.y,g.y,b1); b1 = fmaf(x.z,g.z,b1); b1 = fmaf(x.w,g.w,b1);
                    x = *(const float4*)&kp[j+8];  g = *(const float4*)&sG[j+8];
                    b2 = fmaf(x.x,g.x,b2); b2 = fmaf(x.y,g.y,b2); b2 = fmaf(x.z,g.z,b2); b2 = fmaf(x.w,g.w,b2);
                    x = *(const float4*)&kp[j+12]; g = *(const float4*)&sG[j+12];
                    b3 = fmaf(x.x,g.x,b3); b3 = fmaf(x.y,g.y,b3); b3 = fmaf(x.z,g.z,b3); b3 = fmaf(x.w,g.w,b3);
                }
                float t = (b0 + b1) + (b2 + b3);
                sU[tid] = (maskSelf > 0.f) ? NEGV : 10.0f * tanhf(t);
            }
            asm volatile("bar.sync 1, 128;" ::: "memory");

            if (warp == 0) {
                #pragma unroll
                for (int k = 0; k < 4; k++) uv[k] = sU[lane + 32*k];
                #pragma unroll
                for (int k = 0; k < 4; k++) {
                    int n = lane + 32*k;
                    if (uv[k] > vmax) { vmax = uv[k]; imaxr = n; }
                }
                #pragma unroll
                for (int o = 16; o; o >>= 1) {
                    float ov = __shfl_down_sync(0xffffffffu, vmax, o);
                    int   oi = __shfl_down_sync(0xffffffffu, imaxr, o);
                    if (ov > vmax || (ov == vmax && oi < imaxr)) { vmax = ov; imaxr = oi; }
                }
                vmax  = __shfl_sync(0xffffffffu, vmax, 0);
                imaxr = __shfl_sync(0xffffffffu, imaxr, 0);
                if (lane == 0) sIdx = imaxr;
            }
        }
        __syncthreads();   // publish sIdx

        // ---- update phase: ALL warps replicate state; warp0 also does logp ----
        int im = sIdx;
        int visPre = vis;

        float seld = sDem[im];
        float capNew = (im == 0) ? base_cap : (cap - seld);
        cap = capNew;

        {   // mask1 bits + vis (identical in every warp)
            unsigned own = (lane == (im & 31)) ? 1u : 0u;
            unsigned wasSet = own ? ((m1bits >> (im >> 5)) & 1u) : 0u;
            unsigned bal = __ballot_sync(0xffffffffu, own && im > 0 && !wasSet);
            if (bal) vis += 1;
            if (own && im > 0) m1bits |= 1u << (im >> 5);
        }

        {   // mask regs
            int cnt = 0;
            #pragma unroll
            for (int k = 0; k < 4; k++) {
                int n = lane + 32*k;
                float m1v = ((m1bits >> k) & 1u) ? 1.f : 0.f;
                float m = fmaxf(m1v, (demreg[k] > capNew) ? 1.f : 0.f);
                unsigned bal = __ballot_sync(0xffffffffu, (n >= 1 && n < 100) && m == 0.f);
                cnt += __popc(bal);
                maskreg[k] = m;
            }
            float m0 = (cnt == 0) ? 0.f : ((im == 0) ? 1.f : 0.f);
            if (lane == 0) maskreg[0] = m0;
            maskSelf = (tid == 0) ? m0
                     : fmaxf(((m1bits >> warp) & 1u) ? 1.f : 0.f,
                             (demSelf > capNew) ? 1.f : 0.f);
        }

        // q for next step (uses updated cap, per reference carry)
        if (tid < 128) sQ[tid] = sQe[im*NPAD + tid] + sWc[tid]*capNew + sQp[tid];

        // warp0: action + logp (overlaps other warps' work; no trailing barrier)
        if (warp == 0) {
            float lsum = 0.f;
            #pragma unroll
            for (int k = 0; k < 4; k++) {
                int n = lane + 32*k;
                if (n < 100) lsum += __expf(uv[k] - vmax);
            }
            #pragma unroll
            for (int o = 16; o; o >>= 1) lsum += __shfl_xor_sync(0xffffffffu, lsum, o);
            if (lane == 0) {
                float logp = -logf(lsum);
                if (visPre < 99) logTot += logp;
                out[(size_t)b*STEPS + s] = (float)im;
            }
        }

        int doneFlag = (vis == 99) && (im == 0);   // absorbing state: all future actions = 0
        __syncthreads();
        if (doneFlag) { sStop = s + 1; break; }
    }

    // zero-fill remaining actions (exact: absorbing state always selects depot, logp gated)
    for (int j = sStop + tid; j < STEPS; j += 256) out[(size_t)b*STEPS + j] = 0.f;
    if (tid == 0) out[(size_t)BB*STEPS + b] = logTot;
}

// ======================= launcher ===========================================
extern "C" void kernel_launch(void* const* d_in, const int* in_sizes, int n_in,
                              void* d_out, int out_size)
{
    const float* enc      = (const float*)d_in[0];
    const float* pool     = (const float*)d_in[1];
    const float* capacity = (const float*)d_in[2];
    const float* demand   = (const float*)d_in[3];
    const float* fc_w     = (const float*)d_in[4];
    const float* fc1_w    = (const float*)d_in[5];
    const float* Wq       = (const float*)d_in[6];
    const float* Wk       = (const float*)d_in[7];
    const float* Wv       = (const float*)d_in[8];
    const float* Wo       = (const float*)d_in[9];
    const float* Wk2      = (const float*)d_in[10];
    float* out = (float*)d_out;

    cudaFuncSetAttribute(gemm_kernel,   cudaFuncAttributeMaxDynamicSharedMemorySize, GEMM_SMEM);
    cudaFuncSetAttribute(decode_kernel, cudaFuncAttributeMaxDynamicSharedMemorySize, DEC_SMEM);

    fold_kernel<<<dim3(128, 3), 132>>>(fc_w, fc1_w, Wq, Wo, Wk2);
    gemm_kernel<<<dim3((BB*NN)/GM_TILE, 5), 256, GEMM_SMEM>>>(enc, pool, Wk, Wv);
    decode_kernel<<<BB, 256, DEC_SMEM>>>(capacity, demand, out);
}

// round 8
// speedup vs baseline: 2.4303x; 2.4303x over previous
#include <cuda_runtime.h>
#include <math.h>

// Problem constants
#define BB   1024
#define NN   100
#define HH   128
#define STEPS 128
#define NEGV -1000000000.0f
#define KT_PAD 105      // transposed K2 row stride (odd*... -> conflict-free scalar reads)

// packed f32x2 helpers (Blackwell FFMA2 — bit-identical per-lane IEEE fma)
#define PK2(d, x, y)  asm("mov.b64 %0, {%1, %2};" : "=l"(d) : "f"(x), "f"(y))
#define UPK2(x, y, d) asm("mov.b64 {%0, %1}, %2;" : "=f"(x), "=f"(y) : "l"(d))
#define FMA2(d, a, b) asm("fma.rn.f32x2 %0, %1, %2, %0;" : "+l"(d) : "l"(a), "l"(b))

// -------- device scratch ----
__device__ float g_K [BB*NN*HH];
__device__ float g_V [BB*NN*HH];
__device__ float g_K2[BB*NN*HH];
__device__ float g_Qe[BB*NN*HH];
__device__ float g_qpool[BB*HH];
__device__ float g_Wqf[HH*(HH+1)];
__device__ float g_WfoldT[HH*HH];
__device__ float g_Wpq[HH*HH];
__device__ float g_M [(size_t)BB*NN*8*NN];  // [b][i][h][n]  (C3 folded in)
__device__ float g_C2[BB*8*NN];             // [b][h][n]

// ======================= fold kernel =================================
__global__ void fold_kernel(const float* __restrict__ fc_w,
                            const float* __restrict__ fc1_w,
                            const float* __restrict__ Wq,
                            const float* __restrict__ Wo,
                            const float* __restrict__ Wk2)
{
    int mat = blockIdx.y;
    int r   = blockIdx.x;
    int j   = threadIdx.x;
    if (mat == 0) {
        if (j < 129) {
            float acc = 0.f;
            #pragma unroll 8
            for (int i = 0; i < 128; i++) acc += Wq[r*128 + i] * fc_w[i*129 + j];
            g_Wqf[r*129 + j] = 0.25f * acc;
        }
    } else if (mat == 1) {
        if (j < 128) {
            float acc = 0.f;
            #pragma unroll 8
            for (int i = 0; i < 128; i++) acc += Wk2[i*128 + j] * Wo[i*128 + r];
            g_WfoldT[r*128 + j] = (1.0f / sqrtf(128.0f)) * acc;
        }
    } else {
        if (j < 128) {
            float acc = 0.f;
            #pragma unroll 8
            for (int i = 0; i < 128; i++) acc += Wq[r*128 + i] * fc1_w[i*128 + j];
            g_Wpq[r*128 + j] = 0.25f * acc;
        }
    }
}

// ======================= GEMM: out = A @ W^T (FFMA2) ========================
#define GM_TILE 64
#define GEMM_SMEM ((128*132 + GM_TILE*132) * 4)

__global__ __launch_bounds__(256) void gemm_kernel(const float* __restrict__ enc,
                                                   const float* __restrict__ pool,
                                                   const float* __restrict__ Wk,
                                                   const float* __restrict__ Wv)
{
    extern __shared__ float sm[];
    float* sW = sm;
    float* sA = sm + 128*132;

    int slice = blockIdx.y;
    const float* A; const float* W; float* O; int rows; int ldw = 128;
    if      (slice == 0) { A = enc;  W = Wk;       O = g_K;     rows = BB*NN; }
    else if (slice == 1) { A = enc;  W = Wv;       O = g_V;     rows = BB*NN; }
    else if (slice == 2) { A = enc;  W = g_WfoldT; O = g_K2;    rows = BB*NN; }
    else if (slice == 3) { A = enc;  W = g_Wqf;    O = g_Qe;    rows = BB*NN; ldw = 129; }
    else                 { A = pool; W = g_Wpq;    O = g_qpool; rows = BB;    }

    int row0 = blockIdx.x * GM_TILE;
    if (row0 >= rows) return;
    int tid = threadIdx.x;

    for (int i = tid; i < 128*128; i += 256) {
        int c = i >> 7, m = i & 127;
        sW[m*132 + c] = W[c*ldw + m];
    }
    for (int i = tid; i < GM_TILE*128; i += 256) {
        int r = i >> 7, k = i & 127;
        sA[r*132 + k] = A[(row0 + r)*128 + k];
    }
    __syncthreads();

    int warp = tid >> 5, lane = tid & 31;
    int r0 = warp * 8, c0 = lane * 4;

    unsigned long long accp[4][4];
    #pragma unroll
    for (int c = 0; c < 4; c++)
        #pragma unroll
        for (int t = 0; t < 4; t++) PK2(accp[c][t], 0.f, 0.f);

    #pragma unroll 4
    for (int k = 0; k < 128; k++) {
        float4 w4 = *(const float4*)&sW[k*132 + c0];
        unsigned long long wd[4];
        PK2(wd[0], w4.x, w4.x); PK2(wd[1], w4.y, w4.y);
        PK2(wd[2], w4.z, w4.z); PK2(wd[3], w4.w, w4.w);
        unsigned long long ap[4];
        #pragma unroll
        for (int t = 0; t < 4; t++) {
            float a0 = sA[(r0 + 2*t    )*132 + k];
            float a1 = sA[(r0 + 2*t + 1)*132 + k];
            PK2(ap[t], a0, a1);
        }
        #pragma unroll
        for (int c = 0; c < 4; c++)
            #pragma unroll
            for (int t = 0; t < 4; t++) FMA2(accp[c][t], ap[t], wd[c]);
    }

    #pragma unroll
    for (int t = 0; t < 4; t++) {
        float4 v0, v1;
        UPK2(v0.x, v1.x, accp[0][t]);
        UPK2(v0.y, v1.y, accp[1][t]);
        UPK2(v0.z, v1.z, accp[2][t]);
        UPK2(v0.w, v1.w, accp[3][t]);
        *(float4*)&O[(size_t)(row0 + r0 + 2*t    )*128 + c0] = v0;
        *(float4*)&O[(size_t)(row0 + r0 + 2*t + 1)*128 + c0] = v1;
    }
}

// ======================= score precompute ===================================
// M'[b,i,h,n] = dot16(Qe[i,h],K[n,h]) + dot16(qpool_h,K[n,h]);  C2 = dot16(K,Wc)
#define SP_SMEM (NN*128*4)
__global__ __launch_bounds__(256, 2) void score_pre_kernel()
{
    extern __shared__ float sQe[];
    int b = blockIdx.x, tid = threadIdx.x;
    int h = tid >> 5, lane = tid & 31;

    const float* qe = g_Qe + (size_t)b*NN*HH;
    for (int j = tid; j < NN*HH/4; j += 256)
        *(float4*)&sQe[j*4] = ((const float4*)qe)[j];

    float kr[4][16];
    float wc[16], qp[16];
    #pragma unroll
    for (int j = 0; j < 16; j++) {
        wc[j] = g_Wqf[(h*16+j)*129 + 128];
        qp[j] = g_qpool[b*HH + h*16 + j];
    }
    #pragma unroll
    for (int k = 0; k < 4; k++) {
        int n = lane + 32*k;
        if (n < NN) {
            const float* kp = g_K + (size_t)b*NN*HH + (size_t)n*HH + h*16;
            #pragma unroll
            for (int j = 0; j < 16; j += 4) {
                float4 v = *(const float4*)&kp[j];
                kr[k][j]=v.x; kr[k][j+1]=v.y; kr[k][j+2]=v.z; kr[k][j+3]=v.w;
            }
        }
    }
    float a3s[4];
    #pragma unroll
    for (int k = 0; k < 4; k++) {
        int n = lane + 32*k;
        a3s[k] = 0.f;
        if (n < NN) {
            float a2 = 0.f, a3 = 0.f;
            #pragma unroll
            for (int j = 0; j < 16; j++) { a2 += kr[k][j]*wc[j]; a3 += kr[k][j]*qp[j]; }
            g_C2[((size_t)b*8 + h)*NN + n] = a2;
            a3s[k] = a3;
        }
    }
    __syncthreads();

    float* Mb = g_M + (size_t)b*NN*8*NN;
    for (int i = 0; i < NN; i++) {
        float q[16];
        #pragma unroll
        for (int j = 0; j < 16; j += 4) {
            float4 v = *(const float4*)&sQe[i*128 + h*16 + j];
            q[j]=v.x; q[j+1]=v.y; q[j+2]=v.z; q[j+3]=v.w;
        }
        #pragma unroll
        for (int k = 0; k < 4; k++) {
            int n = lane + 32*k;
            if (n < NN) {
                float acc = 0.f;
                #pragma unroll
                for (int j = 0; j < 16; j++) acc += kr[k][j]*q[j];
                Mb[((size_t)i*8 + h)*NN + n] = acc + a3s[k];
            }
        }
    }
}

// ======================= decode kernel ======================================
// smem: sK2T 128*105=13440 + sAttn 832 + sRden 8 + sPartA 256 (sU aliased at +128)
//     + sG 128 = 14664 floats (58.7 KB) -> 3 CTAs/SM.
// Mask/mask1/vis/cap state replicated in registers in every warp.
#define DEC_SMEM_FLOATS (128*KT_PAD + 832 + 8 + 256 + 128)
#define DEC_SMEM (DEC_SMEM_FLOATS * 4)

__global__ __launch_bounds__(256, 3) void decode_kernel(const float* __restrict__ capacity,
                                                        const float* __restrict__ demand,
                                                        float* __restrict__ out)
{
    extern __shared__ float sm[];
    float* sK2T  = sm;                    // [128][105]  sK2T[d*105 + n] = K2[n][d]
    float* sAttn = sK2T  + 128*KT_PAD;    // [8][104] halves at +0/+52 (unnormalized e)
    float* sRden = sAttn + 832;           // 8
    float* sPartA= sRden + 8;             // 256 ; sU aliases sPartA+128 (after G consumed)
    float* sG    = sPartA+ 256;           // 128
    float* sU    = sPartA + 128;          // 100 used

    int b = blockIdx.x, tid = threadIdx.x;
    int warp = tid >> 5, lane = tid & 31;
    int d = tid & 127, half = tid >> 7, hh = d >> 4;

    // ---- loads ----
    {   // K2 transposed into smem
        const float4* gK2 = (const float4*)(g_K2 + (size_t)b*NN*HH);
        for (int j = tid; j < NN*HH/4; j += 256) {
            int n = j >> 5; int c = (j & 31) << 2;
            float4 v = gK2[j];
            sK2T[(c+0)*KT_PAD + n] = v.x;
            sK2T[(c+1)*KT_PAD + n] = v.y;
            sK2T[(c+2)*KT_PAD + n] = v.z;
            sK2T[(c+3)*KT_PAD + n] = v.w;
        }
    }
    float vreg[50];
    {
        const float* vg = g_V + (size_t)b*NN*HH + (size_t)(half*50)*HH + d;
        #pragma unroll
        for (int i = 0; i < 50; i++) vreg[i] = vg[i*HH];
    }
    float demreg[4];
    #pragma unroll
    for (int k = 0; k < 4; k++) {
        int n = lane + 32*k;
        demreg[k] = (n < 100) ? demand[b*NN + n] : 0.f;
    }
    float demSelf = (tid < 100) ? demand[b*NN + tid] : 0.f;

    float c2reg[4];
    #pragma unroll
    for (int k = 0; k < 4; k++) {
        int n = lane + 32*k;
        c2reg[k] = (n < 100) ? g_C2[(size_t)b*800 + warp*100 + n] : 0.f;
    }
    float mrow[4];
    {
        const float* mp = g_M + ((size_t)b*NN*8 + warp)*NN;
        #pragma unroll
        for (int k = 0; k < 4; k++) { int n = lane + 32*k; mrow[k] = (n < NN) ? mp[n] : 0.f; }
    }

    const float base_cap = capacity[0];
    float cap = capacity[b];

    // ---- initial replicated mask state (index=0, mask1=0, go_depot=1) ----
    unsigned m1bits = 0; int vis = 0;
    float depotMask;
    {
        int cnt = 0;
        #pragma unroll
        for (int k = 0; k < 4; k++) {
            int n = lane + 32*k;
            bool avail = (n >= 1 && n < 100) && !(demreg[k] > cap);
            cnt += __popc(__ballot_sync(0xffffffffu, avail));
        }
        depotMask = (cnt == 0) ? 0.f : 1.f;
    }
    __syncthreads();

    float logTot = 0.f;
    int sStop = STEPS;

    for (int s = 0; s < STEPS; s++) {
        // ---- B: e = exp(M'[im] + cap*c2) unnormalized; per-head 1/sum ----
        {
            float e[4]; float sum = 0.f;
            #pragma unroll
            for (int k = 0; k < 4; k++) {
                int n = lane + 32*k;
                float ee = 0.f;
                if (n < 100) {
                    float m1v = (float)((m1bits >> k) & 1u);
                    bool masked = (n == 0) ? (depotMask > 0.f)
                                           : (m1v > 0.f || demreg[k] > cap);
                    float v = masked ? NEGV : fmaf(cap, c2reg[k], mrow[k]);
                    ee = __expf(v);
                }
                e[k] = ee; sum += ee;
            }
            #pragma unroll
            for (int o = 16; o; o >>= 1) sum += __shfl_xor_sync(0xffffffffu, sum, o);
            #pragma unroll
            for (int k = 0; k < 4; k++) {
                int n = lane + 32*k;
                if (n < 100) sAttn[warp*104 + n + ((n >= 50) ? 2 : 0)] = e[k];
            }
            if (lane == 0) sRden[warp] = 1.0f / sum;
        }
        __syncthreads();

        // ---- C: glimpse partials (V in regs, 4 accumulators) ----
        {
            const float* an = sAttn + hh*104 + half*52;
            float a0 = 0.f, a1 = 0.f, a2 = 0.f, a3 = 0.f;
            #pragma unroll
            for (int i = 0; i < 48; i += 4) {
                float4 a4 = *(const float4*)&an[i];
                a0 = fmaf(a4.x, vreg[i],   a0);
                a1 = fmaf(a4.y, vreg[i+1], a1);
                a2 = fmaf(a4.z, vreg[i+2], a2);
                a3 = fmaf(a4.w, vreg[i+3], a3);
            }
            a0 = fmaf(an[48], vreg[48], a0);
            a1 = fmaf(an[49], vreg[49], a1);
            sPartA[tid] = (a0 + a1) + (a2 + a3);
        }
        __syncthreads();

        // ---- G: combine halves, deferred 1/sum ----
        if (tid < 128) sG[tid] = (sPartA[tid] + sPartA[tid + 128]) * sRden[hh];
        __syncthreads();

        // ---- D: u[n] = 10*tanh(K2'[n].g), transposed conflict-free reads ----
        if (tid < 100) {
            float b0 = 0.f, b1 = 0.f, b2 = 0.f, b3 = 0.f;
            const float* kp = sK2T + tid;
            #pragma unroll
            for (int j = 0; j < 128; j += 4) {
                b0 = fmaf(kp[(j  )*KT_PAD], sG[j  ], b0);
                b1 = fmaf(kp[(j+1)*KT_PAD], sG[j+1], b1);
                b2 = fmaf(kp[(j+2)*KT_PAD], sG[j+2], b2);
                b3 = fmaf(kp[(j+3)*KT_PAD], sG[j+3], b3);
            }
            float t = (b0 + b1) + (b2 + b3);
            float m1v = (float)((m1bits >> warp) & 1u);
            bool masked = (tid == 0) ? (depotMask > 0.f)
                                     : (m1v > 0.f || demSelf > cap);
            sU[tid] = masked ? NEGV : 10.0f * tanhf(t);
        }
        __syncthreads();

        // ---- update: EVERY warp replicates argmax + state; warp0 adds logp ----
        float uv[4]; float vmax = -INFINITY; int im = 0;
        #pragma unroll
        for (int k = 0; k < 4; k++) {
            int n = lane + 32*k;
            uv[k] = (n < 100) ? sU[n] : -INFINITY;
            if (uv[k] > vmax) { vmax = uv[k]; im = n; }
        }
        #pragma unroll
        for (int o = 16; o; o >>= 1) {
            float ov = __shfl_down_sync(0xffffffffu, vmax, o);
            int   oi = __shfl_down_sync(0xffffffffu, im, o);
            if (ov > vmax || (ov == vmax && oi < im)) { vmax = ov; im = oi; }
        }
        vmax = __shfl_sync(0xffffffffu, vmax, 0);
        im   = __shfl_sync(0xffffffffu, im, 0);

        // prefetch next M row immediately (per-warp head row)
        {
            const float* mp = g_M + (((size_t)b*NN + im)*8 + warp)*NN;
            #pragma unroll
            for (int k = 0; k < 4; k++) { int n = lane + 32*k; if (n < NN) mrow[k] = mp[n]; }
        }

        int visPre = vis;
        // demand[im] via select + shuffle (replicated)
        int kv = im >> 5;
        float dsel = (kv == 0) ? demreg[0] : (kv == 1) ? demreg[1]
                   : (kv == 2) ? demreg[2] : demreg[3];
        float seld = __shfl_sync(0xffffffffu, dsel, im & 31);
        float capNew = (im == 0) ? base_cap : (cap - seld);
        cap = capNew;

        // mask1 bits + vis (identical in every warp)
        {
            bool own = (lane == (im & 31));
            bool wasSet = ((m1bits >> kv) & 1u) != 0u;
            unsigned bal = __ballot_sync(0xffffffffu, own && im > 0 && !wasSet);
            if (bal) vis += 1;
            if (own && im > 0) m1bits |= 1u << kv;
        }

        // depot mask from availability count
        {
            int cnt = 0;
            #pragma unroll
            for (int k = 0; k < 4; k++) {
                int n = lane + 32*k;
                bool avail = (n >= 1 && n < 100) &&
                             !(((m1bits >> k) & 1u) || (demreg[k] > capNew));
                cnt += __popc(__ballot_sync(0xffffffffu, avail));
            }
            depotMask = (cnt == 0) ? 0.f : ((im == 0) ? 1.f : 0.f);
        }

        // warp0: logp + action store (overlaps other warps' progress)
        if (warp == 0) {
            float lsum = 0.f;
            #pragma unroll
            for (int k = 0; k < 4; k++) {
                int n = lane + 32*k;
                if (n < 100) lsum += __expf(uv[k] - vmax);
            }
            #pragma unroll
            for (int o = 16; o; o >>= 1) lsum += __shfl_xor_sync(0xffffffffu, lsum, o);
            if (lane == 0) {
                float logp = -logf(lsum);
                if (visPre < 99) logTot += logp;
                out[(size_t)b*STEPS + s] = (float)im;
            }
        }

        if (vis == 99 && im == 0) { sStop = s + 1; break; }  // absorbing state
    }

    // zero-fill remaining actions (absorbing state always selects depot; logp gated)
    for (int j = sStop + tid; j < STEPS; j += 256) out[(size_t)b*STEPS + j] = 0.f;
    if (tid == 0) out[(size_t)BB*STEPS + b] = logTot;
}

// ======================= launcher ===========================================
extern "C" void kernel_launch(void* const* d_in, const int* in_sizes, int n_in,
                              void* d_out, int out_size)
{
    const float* enc      = (const float*)d_in[0];
    const float* pool     = (const float*)d_in[1];
    const float* capacity = (const float*)d_in[2];
    const float* demand   = (const float*)d_in[3];
    const float* fc_w     = (const float*)d_in[4];
    const float* fc1_w    = (const float*)d_in[5];
    const float* Wq       = (const float*)d_in[6];
    const float* Wk       = (const float*)d_in[7];
    const float* Wv       = (const float*)d_in[8];
    const float* Wo       = (const float*)d_in[9];
    const float* Wk2      = (const float*)d_in[10];
    float* out = (float*)d_out;

    cudaFuncSetAttribute(gemm_kernel,      cudaFuncAttributeMaxDynamicSharedMemorySize, GEMM_SMEM);
    cudaFuncSetAttribute(score_pre_kernel, cudaFuncAttributeMaxDynamicSharedMemorySize, SP_SMEM);
    cudaFuncSetAttribute(decode_kernel,    cudaFuncAttributeMaxDynamicSharedMemorySize, DEC_SMEM);

    fold_kernel<<<dim3(128, 3), 132>>>(fc_w, fc1_w, Wq, Wo, Wk2);
    gemm_kernel<<<dim3((BB*NN)/GM_TILE, 5), 256, GEMM_SMEM>>>(enc, pool, Wk, Wv);
    score_pre_kernel<<<BB, 256, SP_SMEM>>>();
    decode_kernel<<<BB, 256, DEC_SMEM>>>(capacity, demand, out);
}

// round 9
// speedup vs baseline: 2.7186x; 1.1186x over previous
#include <cuda_runtime.h>
#include <math.h>

// Problem constants
#define BB   1024
#define NN   100
#define HH   128
#define STEPS 128
#define NEGV -1000000000.0f
#define NPAD 132

// packed f32x2 helpers (Blackwell FFMA2 — bit-identical per-lane IEEE fma)
#define PK2(d, x, y)  asm("mov.b64 %0, {%1, %2};" : "=l"(d) : "f"(x), "f"(y))
#define UPK2(x, y, d) asm("mov.b64 {%0, %1}, %2;" : "=f"(x), "=f"(y) : "l"(d))
#define FMA2(d, a, b) asm("fma.rn.f32x2 %0, %1, %2, %0;" : "+l"(d) : "l"(a), "l"(b))

// -------- device scratch ----
__device__ float g_K [BB*NN*HH];
__device__ float g_V [BB*NN*HH];
__device__ float g_K2[BB*NN*HH];
__device__ float g_Qe[BB*NN*HH];
__device__ float g_qpool[BB*HH];
__device__ float g_Wqf[HH*(HH+1)];
__device__ float g_WfoldT[HH*HH];
__device__ float g_Wpq[HH*HH];
__device__ float g_M [(size_t)BB*NN*8*NN];  // [b][i][h][n]  (C3 folded in)
__device__ float g_C2[BB*8*NN];             // [b][h][n]

// ======================= fold kernel =================================
__global__ void fold_kernel(const float* __restrict__ fc_w,
                            const float* __restrict__ fc1_w,
                            const float* __restrict__ Wq,
                            const float* __restrict__ Wo,
                            const float* __restrict__ Wk2)
{
    int mat = blockIdx.y;
    int r   = blockIdx.x;
    int j   = threadIdx.x;
    if (mat == 0) {
        if (j < 129) {
            float acc = 0.f;
            #pragma unroll 8
            for (int i = 0; i < 128; i++) acc += Wq[r*128 + i] * fc_w[i*129 + j];
            g_Wqf[r*129 + j] = 0.25f * acc;
        }
    } else if (mat == 1) {
        if (j < 128) {
            float acc = 0.f;
            #pragma unroll 8
            for (int i = 0; i < 128; i++) acc += Wk2[i*128 + j] * Wo[i*128 + r];
            g_WfoldT[r*128 + j] = (1.0f / sqrtf(128.0f)) * acc;
        }
    } else {
        if (j < 128) {
            float acc = 0.f;
            #pragma unroll 8
            for (int i = 0; i < 128; i++) acc += Wq[r*128 + i] * fc1_w[i*128 + j];
            g_Wpq[r*128 + j] = 0.25f * acc;
        }
    }
}

// ======================= GEMM: out = A @ W^T (FFMA2, A transposed in smem) ==
#define GM_TILE 64
#define ATPAD 68
#define GEMM_SMEM ((128*132 + 128*ATPAD) * 4)

__global__ __launch_bounds__(256) void gemm_kernel(const float* __restrict__ enc,
                                                   const float* __restrict__ pool,
                                                   const float* __restrict__ Wk,
                                                   const float* __restrict__ Wv)
{
    extern __shared__ float sm[];
    float* sW  = sm;                 // [128][132]  sW[k*132 + c] = W[c][k]
    float* sAT = sm + 128*132;       // [128][68]   sAT[k*68 + r] = A[row0+r][k]

    int slice = blockIdx.y;
    const float* A; const float* W; float* O; int rows; int ldw = 128;
    if      (slice == 0) { A = enc;  W = Wk;       O = g_K;     rows = BB*NN; }
    else if (slice == 1) { A = enc;  W = Wv;       O = g_V;     rows = BB*NN; }
    else if (slice == 2) { A = enc;  W = g_WfoldT; O = g_K2;    rows = BB*NN; }
    else if (slice == 3) { A = enc;  W = g_Wqf;    O = g_Qe;    rows = BB*NN; ldw = 129; }
    else                 { A = pool; W = g_Wpq;    O = g_qpool; rows = BB;    }

    int row0 = blockIdx.x * GM_TILE;
    if (row0 >= rows) return;
    int tid = threadIdx.x;

    for (int i = tid; i < 128*128; i += 256) {
        int c = i >> 7, m = i & 127;
        sW[m*132 + c] = W[c*ldw + m];
    }
    for (int i = tid; i < GM_TILE*128; i += 256) {
        int r = i >> 7, k = i & 127;
        sAT[k*ATPAD + r] = A[(row0 + r)*128 + k];
    }
    __syncthreads();

    int warp = tid >> 5, lane = tid & 31;
    int r0 = warp * 8, c0 = lane * 4;

    unsigned long long accp[4][4];
    #pragma unroll
    for (int c = 0; c < 4; c++)
        #pragma unroll
        for (int t = 0; t < 4; t++) PK2(accp[c][t], 0.f, 0.f);

    #pragma unroll 4
    for (int k = 0; k < 128; k++) {
        float4 w4 = *(const float4*)&sW[k*132 + c0];
        unsigned long long wd[4];
        PK2(wd[0], w4.x, w4.x); PK2(wd[1], w4.y, w4.y);
        PK2(wd[2], w4.z, w4.z); PK2(wd[3], w4.w, w4.w);
        // A rows r0..r0+7 for this k: 2 broadcast float4 loads
        float4 a04 = *(const float4*)&sAT[k*ATPAD + r0];
        float4 a14 = *(const float4*)&sAT[k*ATPAD + r0 + 4];
        unsigned long long ap[4];
        PK2(ap[0], a04.x, a04.y);
        PK2(ap[1], a04.z, a04.w);
        PK2(ap[2], a14.x, a14.y);
        PK2(ap[3], a14.z, a14.w);
        #pragma unroll
        for (int c = 0; c < 4; c++)
            #pragma unroll
            for (int t = 0; t < 4; t++) FMA2(accp[c][t], ap[t], wd[c]);
    }

    #pragma unroll
    for (int t = 0; t < 4; t++) {
        float4 v0, v1;
        UPK2(v0.x, v1.x, accp[0][t]);
        UPK2(v0.y, v1.y, accp[1][t]);
        UPK2(v0.z, v1.z, accp[2][t]);
        UPK2(v0.w, v1.w, accp[3][t]);
        *(float4*)&O[(size_t)(row0 + r0 + 2*t    )*128 + c0] = v0;
        *(float4*)&O[(size_t)(row0 + r0 + 2*t + 1)*128 + c0] = v1;
    }
}

// ======================= score precompute ===================================
// M'[b,i,h,n] = dot16(Qe[i,h],K[n,h]) + dot16(qpool_h,K[n,h]);  C2 = dot16(K,Wc)
#define SP_SMEM (NN*128*4)
__global__ __launch_bounds__(256, 2) void score_pre_kernel()
{
    extern __shared__ float sQe[];
    int b = blockIdx.x, tid = threadIdx.x;
    int h = tid >> 5, lane = tid & 31;

    const float* qe = g_Qe + (size_t)b*NN*HH;
    for (int j = tid; j < NN*HH/4; j += 256)
        *(float4*)&sQe[j*4] = ((const float4*)qe)[j];

    float kr[4][16];
    float wc[16], qp[16];
    #pragma unroll
    for (int j = 0; j < 16; j++) {
        wc[j] = g_Wqf[(h*16+j)*129 + 128];
        qp[j] = g_qpool[b*HH + h*16 + j];
    }
    #pragma unroll
    for (int k = 0; k < 4; k++) {
        int n = lane + 32*k;
        if (n < NN) {
            const float* kp = g_K + (size_t)b*NN*HH + (size_t)n*HH + h*16;
            #pragma unroll
            for (int j = 0; j < 16; j += 4) {
                float4 v = *(const float4*)&kp[j];
                kr[k][j]=v.x; kr[k][j+1]=v.y; kr[k][j+2]=v.z; kr[k][j+3]=v.w;
            }
        }
    }
    float a3s[4];
    #pragma unroll
    for (int k = 0; k < 4; k++) {
        int n = lane + 32*k;
        a3s[k] = 0.f;
        if (n < NN) {
            float a2 = 0.f, a3 = 0.f;
            #pragma unroll
            for (int j = 0; j < 16; j++) { a2 += kr[k][j]*wc[j]; a3 += kr[k][j]*qp[j]; }
            g_C2[((size_t)b*8 + h)*NN + n] = a2;
            a3s[k] = a3;
        }
    }
    __syncthreads();

    float* Mb = g_M + (size_t)b*NN*8*NN;
    for (int i = 0; i < NN; i++) {
        float q[16];
        #pragma unroll
        for (int j = 0; j < 16; j += 4) {
            float4 v = *(const float4*)&sQe[i*128 + h*16 + j];
            q[j]=v.x; q[j+1]=v.y; q[j+2]=v.z; q[j+3]=v.w;
        }
        #pragma unroll
        for (int k = 0; k < 4; k++) {
            int n = lane + 32*k;
            if (n < NN) {
                float acc = 0.f;
                #pragma unroll
                for (int j = 0; j < 16; j++) acc += kr[k][j]*q[j];
                Mb[((size_t)i*8 + h)*NN + n] = acc + a3s[k];
            }
        }
    }
}

// ======================= decode kernel ======================================
// Round-6 structure + XOR-swizzled sK2 (conflict-free float4 in D) + early exit.
// smem ~59 KB -> 3 CTAs/SM.
#define DEC_SMEM_FLOATS (NN*NPAD + 832 + 8 + 256 + 128 + 128 + 104 + 104)
#define DEC_SMEM (DEC_SMEM_FLOATS * 4)

__global__ __launch_bounds__(256, 3) void decode_kernel(const float* __restrict__ capacity,
                                                        const float* __restrict__ demand,
                                                        float* __restrict__ out)
{
    extern __shared__ float sm[];
    float* sK2   = sm;                    // [100][132], chunk-swizzled: c' = c ^ ((n>>3)&7)
    float* sAttn = sK2   + NN*NPAD;       // [8][104] halves at +0/+52 (unnormalized e)
    float* sRden = sAttn + 832;           // 8
    float* sPartA= sRden + 8;             // 256
    float* sG    = sPartA+ 256;           // 128
    float* sU    = sG    + 128;           // 128 (pads 100..127 = -inf)
    float* sMask = sU    + 128;           // 104
    float* sDem  = sMask + 104;           // 104

    __shared__ float sCap;
    __shared__ int   sIdx;
    __shared__ int   sDone;

    int b = blockIdx.x, tid = threadIdx.x;
    int warp = tid >> 5, lane = tid & 31;
    int d = tid & 127, half = tid >> 7, hh = d >> 4;

    // ---- loads ----
    {
        const float4* gK2 = (const float4*)(g_K2 + (size_t)b*NN*HH);
        for (int j = tid; j < NN*HH/4; j += 256) {
            int n = j >> 5; int c4 = j & 31;
            int cs = c4 ^ ((n >> 3) & 7);          // xor-swizzle chunk
            *(float4*)&sK2[n*NPAD + (cs << 2)] = gK2[j];
        }
    }
    float vreg[50];
    {
        const float* vg = g_V + (size_t)b*NN*HH + (size_t)(half*50)*HH + d;
        #pragma unroll
        for (int i = 0; i < 50; i++) vreg[i] = vg[i*HH];
    }
    if (tid < 100) sDem[tid] = demand[b*NN + tid];
    if (tid >= 100 && tid < 128) sU[tid] = -INFINITY;   // argmax pads (never rewritten)
    if (tid == 0) { sCap = capacity[b]; sIdx = 0; sDone = 0; }

    float c2reg[4];
    #pragma unroll
    for (int k = 0; k < 4; k++) {
        int n = lane + 32*k;
        c2reg[k] = (n < 100) ? g_C2[(size_t)b*800 + warp*100 + n] : 0.f;
    }
    float mrow[4];
    {
        const float* mp = g_M + ((size_t)b*NN*8 + warp)*NN;
        #pragma unroll
        for (int k = 0; k < 4; k++) { int n = lane + 32*k; mrow[k] = (n < NN) ? mp[n] : 0.f; }
    }
    __syncthreads();

    const float base_cap = capacity[0];

    // ---- initial mask (index=0, mask1=0, go_depot=1) ----
    if (warp == 0) {
        float cap0 = sCap; int cnt = 0;
        #pragma unroll
        for (int k = 0; k < 4; k++) {
            int n = lane + 32*k;
            if (n >= 1 && n < 100) {
                float m = (sDem[n] > cap0) ? 1.f : 0.f;
                sMask[n] = m;
                if (m == 0.f) cnt++;
            }
        }
        #pragma unroll
        for (int o = 16; o; o >>= 1) cnt += __shfl_xor_sync(0xffffffffu, cnt, o);
        if (lane == 0) sMask[0] = (cnt == 0) ? 0.f : 1.f;
    }
    __syncthreads();

    float logTot = 0.f;
    int   vis    = 0;
    unsigned m1bits = 0;   // warp0: mask1 bits for n = lane + 32k
    int sStop = STEPS;

    for (int s = 0; s < STEPS; s++) {
        // ---- B: e = exp(score) unnormalized; per-head 1/sum ----
        {
            float cap = sCap;
            float e[4]; float sum = 0.f;
            #pragma unroll
            for (int k = 0; k < 4; k++) {
                int n = lane + 32*k;
                float ee = 0.f;
                if (n < 100) {
                    float v = (sMask[n] > 0.f) ? NEGV : fmaf(cap, c2reg[k], mrow[k]);
                    ee = __expf(v);
                }
                e[k] = ee; sum += ee;
            }
            #pragma unroll
            for (int o = 16; o; o >>= 1) sum += __shfl_xor_sync(0xffffffffu, sum, o);
            #pragma unroll
            for (int k = 0; k < 4; k++) {
                int n = lane + 32*k;
                if (n < 100) sAttn[warp*104 + n + ((n >= 50) ? 2 : 0)] = e[k];
            }
            if (lane == 0) sRden[warp] = 1.0f / sum;
        }
        __syncthreads();

        // ---- C: glimpse partials (V in regs, 4 accumulators) ----
        {
            const float* an = sAttn + hh*104 + half*52;
            float a0 = 0.f, a1 = 0.f, a2 = 0.f, a3 = 0.f;
            #pragma unroll
            for (int i = 0; i < 48; i += 4) {
                float4 a4 = *(const float4*)&an[i];
                a0 = fmaf(a4.x, vreg[i],   a0);
                a1 = fmaf(a4.y, vreg[i+1], a1);
                a2 = fmaf(a4.z, vreg[i+2], a2);
                a3 = fmaf(a4.w, vreg[i+3], a3);
            }
            a0 = fmaf(an[48], vreg[48], a0);
            a1 = fmaf(an[49], vreg[49], a1);
            sPartA[tid] = (a0 + a1) + (a2 + a3);
        }
        __syncthreads();

        float uv[4]; float vmax = -INFINITY; int imax = 0;

        // ---- warps 0-3: g-combine (deferred 1/sum), u, argmax ----
        if (tid < 128) {
            sG[tid] = (sPartA[tid] + sPartA[tid + 128]) * sRden[hh];
            asm volatile("bar.sync 1, 128;" ::: "memory");

            if (tid < 100) {
                const float* kp = sK2 + tid*NPAD;
                int sw = ((tid >> 3) & 7) << 2;   // float-index xor for chunk swizzle
                float b0 = 0.f, b1 = 0.f, b2 = 0.f, b3 = 0.f;
                #pragma unroll
                for (int j = 0; j < 128; j += 16) {
                    float4 x, g;
                    x = *(const float4*)&kp[(j     ) ^ sw]; g = *(const float4*)&sG[j];
                    b0 = fmaf(x.x,g.x,b0); b0 = fmaf(x.y,g.y,b0); b0 = fmaf(x.z,g.z,b0); b0 = fmaf(x.w,g.w,b0);
                    x = *(const float4*)&kp[(j +  4) ^ sw]; g = *(const float4*)&sG[j+4];
                    b1 = fmaf(x.x,g.x,b1); b1 = fmaf(x.y,g.y,b1); b1 = fmaf(x.z,g.z,b1); b1 = fmaf(x.w,g.w,b1);
                    x = *(const float4*)&kp[(j +  8) ^ sw]; g = *(const float4*)&sG[j+8];
                    b2 = fmaf(x.x,g.x,b2); b2 = fmaf(x.y,g.y,b2); b2 = fmaf(x.z,g.z,b2); b2 = fmaf(x.w,g.w,b2);
                    x = *(const float4*)&kp[(j + 12) ^ sw]; g = *(const float4*)&sG[j+12];
                    b3 = fmaf(x.x,g.x,b3); b3 = fmaf(x.y,g.y,b3); b3 = fmaf(x.z,g.z,b3); b3 = fmaf(x.w,g.w,b3);
                }
                float t = (b0 + b1) + (b2 + b3);
                sU[tid] = (sMask[tid] > 0.f) ? NEGV : 10.0f * tanhf(t);
            }
            asm volatile("bar.sync 1, 128;" ::: "memory");

            // warp0: argmax + publish sIdx ASAP (sU pads 100..127 are -inf)
            if (warp == 0) {
                #pragma unroll
                for (int k = 0; k < 4; k++) uv[k] = sU[lane + 32*k];
                #pragma unroll
                for (int k = 0; k < 4; k++) {
                    int n = lane + 32*k;
                    if (uv[k] > vmax) { vmax = uv[k]; imax = n; }
                }
                #pragma unroll
                for (int o = 16; o; o >>= 1) {
                    float ov = __shfl_down_sync(0xffffffffu, vmax, o);
                    int   oi = __shfl_down_sync(0xffffffffu, imax, o);
                    if (ov > vmax || (ov == vmax && oi < imax)) { vmax = ov; imax = oi; }
                }
                vmax = __shfl_sync(0xffffffffu, vmax, 0);
                imax = __shfl_sync(0xffffffffu, imax, 0);
                if (lane == 0) sIdx = imax;
            }
        }
        __syncthreads();   // publish sIdx

        // ---- ALL warps: prefetch next M row early (hides DRAM under tail) ----
        {
            int idx = sIdx;
            const float* mp = g_M + (((size_t)b*NN + idx)*8 + warp)*NN;
            #pragma unroll
            for (int k = 0; k < 4; k++) { int n = lane + 32*k; if (n < NN) mrow[k] = mp[n]; }
        }

        // ---- warp0 tail: logp, state, mask (overlaps M prefetch latency) ----
        if (warp == 0) {
            float sum = 0.f;
            #pragma unroll
            for (int k = 0; k < 4; k++) {
                int n = lane + 32*k;
                if (n < 100) sum += __expf(uv[k] - vmax);
            }
            #pragma unroll
            for (int o = 16; o; o >>= 1) sum += __shfl_xor_sync(0xffffffffu, sum, o);

            float capNew = 0.f;
            if (lane == 0) {
                float logp = -logf(sum);
                if (vis < 99) logTot += logp;
                out[(size_t)b*STEPS + s] = (float)imax;
                float seld = sDem[imax];
                capNew = (imax == 0) ? base_cap : (sCap - seld);
                sCap = capNew;
            }
            capNew = __shfl_sync(0xffffffffu, capNew, 0);

            // mask1 (bits) + vis
            int kbit = imax >> 5;
            int owner = (lane == (imax & 31));
            unsigned newly = (owner && imax > 0 && !((m1bits >> kbit) & 1u)) ? 1u : 0u;
            unsigned bal = __ballot_sync(0xffffffffu, newly);
            if (bal) vis += 1;
            if (owner && imax > 0) m1bits |= (1u << kbit);

            int goDepot = (imax == 0);
            int cnt = 0;
            #pragma unroll
            for (int k = 0; k < 4; k++) {
                int n = lane + 32*k;
                if (n >= 1 && n < 100) {
                    float m1v = ((m1bits >> k) & 1u) ? 1.f : 0.f;
                    float m = fmaxf(m1v, (sDem[n] > capNew) ? 1.f : 0.f);
                    sMask[n] = m;
                    if (m == 0.f) cnt++;
                }
            }
            #pragma unroll
            for (int o = 16; o; o >>= 1) cnt += __shfl_xor_sync(0xffffffffu, cnt, o);
            if (lane == 0) {
                sMask[0] = (cnt == 0) ? 0.f : (goDepot ? 1.f : 0.f);
                sDone = (vis == 99 && imax == 0) ? 1 : 0;   // absorbing state
            }
        }
        __syncthreads();

        if (sDone) { sStop = s + 1; break; }
    }

    // zero-fill remaining actions (absorbing state always selects depot; logp gated)
    for (int j = sStop + tid; j < STEPS; j += 256) out[(size_t)b*STEPS + j] = 0.f;
    if (tid == 0) out[(size_t)BB*STEPS + b] = logTot;
}

// ======================= launcher ===========================================
extern "C" void kernel_launch(void* const* d_in, const int* in_sizes, int n_in,
                              void* d_out, int out_size)
{
    const float* enc      = (const float*)d_in[0];
    const float* pool     = (const float*)d_in[1];
    const float* capacity = (const float*)d_in[2];
    const float* demand   = (const float*)d_in[3];
    const float* fc_w     = (const float*)d_in[4];
    const float* fc1_w    = (const float*)d_in[5];
    const float* Wq       = (const float*)d_in[6];
    const float* Wk       = (const float*)d_in[7];
    const float* Wv       = (const float*)d_in[8];
    const float* Wo       = (const float*)d_in[9];
    const float* Wk2      = (const float*)d_in[10];
    float* out = (float*)d_out;

    cudaFuncSetAttribute(gemm_kernel,      cudaFuncAttributeMaxDynamicSharedMemorySize, GEMM_SMEM);
    cudaFuncSetAttribute(score_pre_kernel, cudaFuncAttributeMaxDynamicSharedMemorySize, SP_SMEM);
    cudaFuncSetAttribute(decode_kernel,    cudaFuncAttributeMaxDynamicSharedMemorySize, DEC_SMEM);

    fold_kernel<<<dim3(128, 3), 132>>>(fc_w, fc1_w, Wq, Wo, Wk2);
    gemm_kernel<<<dim3((BB*NN)/GM_TILE, 5), 256, GEMM_SMEM>>>(enc, pool, Wk, Wv);
    score_pre_kernel<<<BB, 256, SP_SMEM>>>();
    decode_kernel<<<BB, 256, DEC_SMEM>>>(capacity, demand, out);
}